// round 16
// baseline (speedup 1.0000x reference)
#include <cuda_runtime.h>
#include <cuda_fp16.h>
#include <cstdint>
#include <math.h>

#define BS 8192
#define LH 20
#define NF 172
#define TF 172
#define DD 860
#define DH 430
#define NROWS (BS*LH)
#define QKN 1720          // q|k only
#define KP1 896
#define KP2 192
#define KF  704           // reduced qkv K: src|dst|edge|time
#define FBLD 1792         // FBAR row stride (2 heads x 896)

// fp16 weight scratch offsets (halfs)
#define W_INPROJ 0                                     // [1720][704]
#define W_ANON   (W_INPROJ + (size_t)QKN*KF)           // [1720][192]
#define W_V      (W_ANON   + (size_t)QKN*KP2)          // [860][896]
#define W_OUTPROJ (W_V     + (size_t)DD*KP1)
#define W_OUTFN  (W_OUTPROJ + (size_t)DD*KP1)
#define W_FC1    (W_OUTFN  + (size_t)NF*KP1)
#define W_FC2    (W_FC1    + (size_t)NF*KP1)
#define W_TOTAL  (W_FC2    + (size_t)NF*KP2)

__device__ __half g_F[(size_t)NROWS * KF];
__device__ __half g_QKV[(size_t)NROWS * QKN];
__device__ __half g_FBAR[(size_t)BS * FBLD];
__device__ __half g_CTXM[(size_t)BS * KP1];
__device__ __half g_OM[(size_t)BS * KP1];
__device__ __half g_X[(size_t)BS * KP1];
__device__ __half g_H1[(size_t)BS * KP2];
__device__ __half g_WR[W_TOTAL];
__device__ __half g_AE[(size_t)128 * KP2];
__device__ __half g_TA[(size_t)128 * QKN];
__device__ int    g_AOFF[(size_t)NROWS];
__device__ int    g_AID[(size_t)NROWS];
__device__ float  g_ZB[QKN];

__device__ __forceinline__ uint32_t smem_u32(const void* p) {
    uint32_t a;
    asm("{ .reg .u64 t; cvta.to.shared.u64 t, %1; cvt.u32.u64 %0, t; }" : "=r"(a) : "l"(p));
    return a;
}
__device__ __forceinline__ void cp16(uint32_t dst, const void* src, int bytes) {
    asm volatile("cp.async.cg.shared.global [%0], [%1], 16, %2;"
                 :: "r"(dst), "l"(src), "r"(bytes));
}
__device__ __forceinline__ void cp_commit() {
    asm volatile("cp.async.commit_group;" ::: "memory");
}
template <int N>
__device__ __forceinline__ void cp_wait() {
    asm volatile("cp.async.wait_group %0;" :: "n"(N) : "memory");
}
__device__ __forceinline__ void mma_f16(float* c, const uint32_t* a, uint32_t b0, uint32_t b1) {
    asm volatile(
        "mma.sync.aligned.m16n8k16.row.col.f32.f16.f16.f32 "
        "{%0,%1,%2,%3}, {%4,%5,%6,%7}, {%8,%9}, {%0,%1,%2,%3};\n"
        : "+f"(c[0]), "+f"(c[1]), "+f"(c[2]), "+f"(c[3])
        : "r"(a[0]), "r"(a[1]), "r"(a[2]), "r"(a[3]), "r"(b0), "r"(b1));
}
__device__ __forceinline__ void ldsm_x4(uint32_t& r0, uint32_t& r1, uint32_t& r2, uint32_t& r3,
                                        uint32_t addr) {
    asm volatile("ldmatrix.sync.aligned.m8n8.x4.shared.b16 {%0,%1,%2,%3}, [%4];"
                 : "=r"(r0), "=r"(r1), "=r"(r2), "=r"(r3) : "r"(addr));
}

// ---------------- fused weight convert (+ anony embedding) ----------------
#define C0 (QKN*688)
#define C1 (C0 + QKN*NF)
#define C2 (C1 + DD*DD)
#define C3 (C2 + DD*DD)
#define C4 (C3 + NF*DD)
#define C5 (C4 + NF*DD)
#define C6 (C5 + NF*NF)
#define C7 (C6 + 21*NF)
__global__ void cvt_all(const float* __restrict__ w_inproj,
                        const float* __restrict__ w_outproj,
                        const float* __restrict__ w_outfn,
                        const float* __restrict__ w_fc1,
                        const float* __restrict__ w_fc2,
                        const float* __restrict__ anony_emb)
{
    int i = blockIdx.x * 256 + threadIdx.x;
    if (i >= C7) return;
    if (i < C0) {
        int r = i / 688, c = i % 688;
        int sc = (c < 344) ? c : c + 172;
        g_WR[W_INPROJ + (size_t)r * KF + c] = __float2half_rn(w_inproj[(size_t)r * DD + sc]);
    } else if (i < C1) {
        int j = i - C0; int r = j / NF, c = j % NF;
        g_WR[W_ANON + (size_t)r * KP2 + c] = __float2half_rn(w_inproj[(size_t)r * DD + 344 + c]);
    } else if (i < C2) {
        int j = i - C1; int r = j / DD, c = j % DD;
        g_WR[W_V + (size_t)r * KP1 + c] = __float2half_rn(w_inproj[(size_t)(QKN + r) * DD + c]);
    } else if (i < C3) {
        int j = i - C2; int r = j / DD, c = j % DD;
        g_WR[W_OUTPROJ + (size_t)r * KP1 + c] = __float2half_rn(w_outproj[j]);
    } else if (i < C4) {
        int j = i - C3; int r = j / DD, c = j % DD;
        g_WR[W_OUTFN + (size_t)r * KP1 + c] = __float2half_rn(w_outfn[j]);
    } else if (i < C5) {
        int j = i - C4; int r = j / DD, c = j % DD;
        g_WR[W_FC1 + (size_t)r * KP1 + c] = __float2half_rn(w_fc1[j]);
    } else if (i < C6) {
        int j = i - C5; int r = j / NF, c = j % NF;
        g_WR[W_FC2 + (size_t)r * KP2 + c] = __float2half_rn(w_fc2[j]);
    } else {
        int j = i - C6; int r = j / NF, c = j % NF;
        g_AE[(size_t)r * KP2 + c] = __float2half_rn(anony_emb[j]);
    }
}

// ---------------- fp16 GEMM, 128x128 tile, 3-stage, 2 CTA/SM, z-batched ----------------
#define GBM 128
#define GBN 128
#define A_BYTES (GBM * 144)
#define B_BYTES (GBN * 144)
#define STAGE_BYTES (A_BYTES + B_BYTES)
#define NSTAGE 3
#define GSMEM (NSTAGE * STAGE_BYTES)

__device__ __forceinline__ void issue_tile(const __half* __restrict__ A,
                                           const __half* __restrict__ B,
                                           uint32_t sstage, int m0, int n0, int k0,
                                           int N, int K, int lda, int t)
{
    #pragma unroll
    for (int i = 0; i < 4; i++) {
        int id = t + (i << 8);
        int row = id >> 3;
        int c8 = (id & 7) << 3;
        const __half* src = A + (size_t)(m0 + row) * lda + k0 + c8;
        cp16(sstage + row * 144 + (id & 7) * 16, src, 16);
    }
    #pragma unroll
    for (int i = 0; i < 4; i++) {
        int id = t + (i << 8);
        int row = id >> 3;
        int c8 = (id & 7) << 3;
        int bytes = (n0 + row < N) ? 16 : 0;
        const __half* src = bytes ? (B + (size_t)(n0 + row) * K + k0 + c8) : B;
        cp16(sstage + A_BYTES + row * 144 + (id & 7) * 16, src, bytes);
    }
}

__global__ void __launch_bounds__(256, 2)
gemm_f16(const __half* __restrict__ A, const __half* __restrict__ B,
         const float* __restrict__ bias,
         __half* __restrict__ C, int ldc,
         float* __restrict__ Cf, int ldcf,
         float* __restrict__ aux,
         int M, int N, int K, int lda, int relu_a,
         const __half* __restrict__ Ta, const int* __restrict__ aoff,
         int zA, int zB, int zBias, int zC)
{
    extern __shared__ __align__(16) char sm[];
    uint32_t sbase = smem_u32(sm);

    int z = blockIdx.z;
    A += (size_t)z * zA;
    B += (size_t)z * zB;
    bias += (size_t)z * zBias;
    if (C) C += (size_t)z * zC;

    int t = threadIdx.x;
    int warp = t >> 5, lane = t & 31;
    int m0 = blockIdx.y * GBM;
    int n0 = blockIdx.x * GBN;
    int mbase = (warp & 1) * 64;
    int nbase = (warp >> 1) * 32;

    uint32_t a_lane = (uint32_t)(lane & 15) * 144 + ((lane >> 4) << 4);
    uint32_t b_lane = (uint32_t)((lane & 7) | ((lane >> 1) & 8)) * 144 + (((lane >> 3) & 1) << 4);

    float acc[4][4][4];
    #pragma unroll
    for (int mi = 0; mi < 4; mi++)
        #pragma unroll
        for (int ni = 0; ni < 4; ni++)
            #pragma unroll
            for (int r = 0; r < 4; r++) acc[mi][ni][r] = 0.0f;

    int KT = K >> 6;

    issue_tile(A, B, sbase, m0, n0, 0, N, K, lda, t);
    cp_commit();
    if (KT > 1) issue_tile(A, B, sbase + STAGE_BYTES, m0, n0, 64, N, K, lda, t);
    cp_commit();

    const __half2 hz = __float2half2_rn(0.0f);

    int scur = 0, snxt = 2;
    for (int kt = 0; kt < KT; kt++) {
        cp_wait<1>();
        __syncthreads();

        if (kt + 2 < KT)
            issue_tile(A, B, sbase + snxt * STAGE_BYTES, m0, n0, (kt + 2) << 6, N, K, lda, t);
        cp_commit();

        uint32_t sA = sbase + scur * STAGE_BYTES;
        uint32_t sB = sA + A_BYTES;

        #pragma unroll
        for (int kk = 0; kk < 4; kk++) {
            uint32_t kof = (uint32_t)kk * 32;
            uint32_t a[4][4];
            #pragma unroll
            for (int mi = 0; mi < 4; mi++)
                ldsm_x4(a[mi][0], a[mi][1], a[mi][2], a[mi][3],
                        sA + (uint32_t)(mbase + mi * 16) * 144 + kof + a_lane);
            if (relu_a) {
                #pragma unroll
                for (int mi = 0; mi < 4; mi++)
                    #pragma unroll
                    for (int q = 0; q < 4; q++) {
                        __half2 h = *reinterpret_cast<__half2*>(&a[mi][q]);
                        h = __hmax2(h, hz);
                        a[mi][q] = *reinterpret_cast<uint32_t*>(&h);
                    }
            }
            uint32_t b[4][2];
            #pragma unroll
            for (int np = 0; np < 2; np++)
                ldsm_x4(b[2*np][0], b[2*np][1], b[2*np+1][0], b[2*np+1][1],
                        sB + (uint32_t)(nbase + np * 16) * 144 + kof + b_lane);
            #pragma unroll
            for (int mi = 0; mi < 4; mi++)
                #pragma unroll
                for (int ni = 0; ni < 4; ni++)
                    mma_f16(acc[mi][ni], a[mi], b[ni][0], b[ni][1]);
        }

        scur = (scur == NSTAGE - 1) ? 0 : scur + 1;
        snxt = (snxt == NSTAGE - 1) ? 0 : snxt + 1;
    }

    #pragma unroll
    for (int mi = 0; mi < 4; mi++) {
        int r0 = m0 + mbase + mi * 16 + (lane >> 2);
        int r1 = r0 + 8;
        int ao0 = aoff ? aoff[r0] : -1;
        int ao1 = aoff ? aoff[r1] : -1;
        #pragma unroll
        for (int ni = 0; ni < 4; ni++) {
            int col = n0 + nbase + ni * 8 + (lane & 3) * 2;
            if (col < N) {
                float b0 = bias[col], b1 = bias[col + 1];
                float v00 = acc[mi][ni][0] + b0, v01 = acc[mi][ni][1] + b1;
                float v10 = acc[mi][ni][2] + b0, v11 = acc[mi][ni][3] + b1;
                if (ao0 >= 0) {
                    float2 ta = __half22float2(*(const __half2*)(Ta + (size_t)ao0 + col));
                    v00 += ta.x; v01 += ta.y;
                }
                if (ao1 >= 0) {
                    float2 ta = __half22float2(*(const __half2*)(Ta + (size_t)ao1 + col));
                    v10 += ta.x; v11 += ta.y;
                }
                if (C) {
                    *(__half2*)(C + (size_t)r0 * ldc + col) = __floats2half2_rn(v00, v01);
                    *(__half2*)(C + (size_t)r1 * ldc + col) = __floats2half2_rn(v10, v11);
                }
                if (Cf) {
                    Cf[(size_t)r0 * ldcf + col]     = v00;
                    Cf[(size_t)r0 * ldcf + col + 1] = v01;
                    Cf[(size_t)r1 * ldcf + col]     = v10;
                    Cf[(size_t)r1 * ldcf + col + 1] = v11;
                }
                if (aux) {
                    aux[(size_t)r0 * N + col]     = v00;
                    aux[(size_t)r0 * N + col + 1] = v01;
                    aux[(size_t)r1 * N + col]     = v10;
                    aux[(size_t)r1 * N + col + 1] = v11;
                }
            }
        }
    }
}

// ---------------- build kernel ----------------
__global__ void build_kernel(const int* __restrict__ nids,
                             const int* __restrict__ hist_nids,
                             const int* __restrict__ aids,
                             const int* __restrict__ eids,
                             const float* __restrict__ ts,
                             const int* __restrict__ dirs,
                             const float* __restrict__ node_emb,
                             const float* __restrict__ edge_emb,
                             const float* __restrict__ anony_emb,
                             const float* __restrict__ time_w,
                             const float* __restrict__ time_b,
                             float* __restrict__ out_pts)
{
    int row = blockIdx.x;
    int b = row / LH, l = row % LH;
    int hn  = hist_nids[row];
    int d   = dirs[row];
    int rn  = nids[b];
    int src = d ? rn : hn;
    int dst = d ? hn : rn;
    int aid = aids[row];
    int eid = eids[row];
    float tlast = ts[b*LH + (LH-1)];
    float dt = tlast - ts[row];
    bool last = (l == LH-1);
    __half* Frow = g_F + (size_t)row * KF;

    for (int c = threadIdx.x; c < 688; c += blockDim.x) {
        float v;
        if (c < 516) {
            if (last) v = 0.0f;
            else if (c < 172) v = node_emb[(size_t)src*NF + c];
            else if (c < 344) v = node_emb[(size_t)dst*NF + (c-172)];
            else              v = edge_emb[(size_t)eid*NF + (c-344)];
        } else {
            int f = c - 516;
            v = cosf(dt * time_w[f] + time_b[f]);
        }
        Frow[c] = __float2half_rn(v);
    }

    if (last) {
        for (int c = threadIdx.x; c < 688; c += blockDim.x) {
            float v;
            if      (c < 172) v = node_emb[(size_t)src*NF + c];
            else if (c < 344) v = node_emb[(size_t)dst*NF + (c-172)];
            else if (c < 516) v = anony_emb[(size_t)aid*NF + (c-344)];
            else              v = edge_emb[(size_t)eid*NF + (c-516)];
            g_X[(size_t)b*KP1 + NF + c] = __float2half_rn(v);
        }
        if (threadIdx.x == 0) out_pts[b] = tlast;
    }
    if (threadIdx.x == 0) {
        int ae = last ? 21 : aid;
        g_AOFF[row] = ae * QKN;
        g_AID[row]  = ae;
    }
}

// ---------------- attention: stacked-gram HMMA, both heads parallel ----------------
#define AST 440                       // halfs per staged row (880B; 55x16B odd -> conflict-free)
#define XTILE (48 * AST)              // halfs per head tile ([Q20;K20;pad])
#define ATTN_SMEM (2 * XTILE * 2)     // 84480 bytes
#define DH2 215

__global__ void __launch_bounds__(256, 2)
attn_kernel(const int* __restrict__ hist_nids)
{
    extern __shared__ __align__(16) __half xs[];   // [2][48*440]
    __shared__ float sc[2][LH][LH];
    __shared__ float ab2[2][LH];
    __shared__ int   msk[LH];
    __shared__ int   aid_s[LH];

    int b = blockIdx.x;
    int t = threadIdx.x;
    int warp = t >> 5, lane = t & 31;
    const __half* qkvb = g_QKV + (size_t)b * LH * QKN;
    const float scale = 0.048224282f;

    if (t < LH) {
        msk[t] = (hist_nids[b*LH + t] == 0 && t != LH-1) ? 1 : 0;
        aid_s[t] = g_AID[b*LH + t];
    }

    // stage both heads: rows 0..19 = Q, rows 20..39 = K (rows 40..47 unstaged, discarded)
    const __half2 hz2 = __float2half2_rn(0.0f);
    for (int i = t; i < 2 * 40 * (AST/2); i += 256) {
        int h  = i / (40 * (AST/2));
        int rem = i % (40 * (AST/2));
        int j  = rem / (AST/2);
        int c2 = rem % (AST/2);
        __half2 v = hz2;
        if (c2 < DH2) {
            int jr = (j < LH) ? j : j - LH;
            int mo = (j < LH) ? 0 : 860;
            v = *((const __half2*)(qkvb + (size_t)jr * QKN + mo + h * DH) + c2);
        }
        *((__half2*)(xs + h * XTILE + j * AST) + c2) = v;
    }
    __syncthreads();

    // HMMA: warp w -> head h = w>>2, tile (mb, nb)
    {
        int h = warp >> 2;
        int w2 = warp & 3;
        int mb = (w2 & 1) * 16;
        int nb = 16 + (w2 >> 1) * 16;
        uint32_t xb = smem_u32(xs) + (uint32_t)h * (XTILE * 2);
        uint32_t a_lane = (uint32_t)(lane & 15) * 880 + ((lane >> 4) << 4);
        uint32_t b_lane = (uint32_t)((lane & 7) | ((lane >> 1) & 8)) * 880 + (((lane >> 3) & 1) << 4);
        float acc0[4] = {0.f, 0.f, 0.f, 0.f};
        float acc1[4] = {0.f, 0.f, 0.f, 0.f};
        uint32_t aaddr = xb + (uint32_t)mb * 880 + a_lane;
        uint32_t baddr = xb + (uint32_t)nb * 880 + b_lane;
        #pragma unroll
        for (int ks = 0; ks < 27; ks++) {
            uint32_t kof = (uint32_t)ks * 32;
            uint32_t a[4], b0r0, b0r1, b1r0, b1r1;
            ldsm_x4(a[0], a[1], a[2], a[3], aaddr + kof);
            ldsm_x4(b0r0, b0r1, b1r0, b1r1, baddr + kof);
            mma_f16(acc0, a, b0r0, b0r1);
            mma_f16(acc1, a, b1r0, b1r1);
        }
        int r0 = mb + (lane >> 2), r1 = r0 + 8;
        int c0 = nb + (lane & 3) * 2 - LH;    // K-row index
        if (r0 < LH) {
            if (c0     >= 0 && c0     < LH) sc[h][r0][c0]     = acc0[0] * scale;
            if (c0 + 1 >= 0 && c0 + 1 < LH) sc[h][r0][c0 + 1] = acc0[1] * scale;
            if (c0 + 8 >= 0 && c0 + 8 < LH) sc[h][r0][c0 + 8] = acc1[0] * scale;
            if (c0 + 9 >= 0 && c0 + 9 < LH) sc[h][r0][c0 + 9] = acc1[1] * scale;
        }
        if (r1 < LH) {
            if (c0     >= 0 && c0     < LH) sc[h][r1][c0]     = acc0[2] * scale;
            if (c0 + 1 >= 0 && c0 + 1 < LH) sc[h][r1][c0 + 1] = acc0[3] * scale;
            if (c0 + 8 >= 0 && c0 + 8 < LH) sc[h][r1][c0 + 8] = acc1[2] * scale;
            if (c0 + 9 >= 0 && c0 + 9 < LH) sc[h][r1][c0 + 9] = acc1[3] * scale;
        }
    }
    __syncthreads();

    // softmax: warps 0 (head 0) and 4 (head 1) in parallel
    if ((warp & 3) == 0 && lane < LH) {
        int h = warp >> 2;
        int i = lane;
        float mx = -1e30f;
        #pragma unroll
        for (int j = 0; j < LH; j++)
            if (!msk[j]) mx = fmaxf(mx, sc[h][i][j]);
        float e[LH]; float s = 0.f;
        #pragma unroll
        for (int j = 0; j < LH; j++) {
            float ev = msk[j] ? 0.f : __expf(sc[h][i][j] - mx);
            e[j] = ev; s += ev;
        }
        float inv = 1.f / s;
        #pragma unroll
        for (int j = 0; j < LH; j++) sc[h][i][j] = e[j] * inv;
    }
    __syncthreads();

    if ((warp & 3) == 0 && lane < LH) {
        int h = warp >> 2;
        int j = lane; float s = 0.f;
        #pragma unroll
        for (int i = 0; i < LH; i++) s += sc[h][i][j];
        ab2[h][j] = s * (1.0f / LH);
    }
    __syncthreads();

    // fbar_h = sum_j ab2[h][j] * full_j (orig 860-col layout) -> FBAR
    const __half* Fb = g_F + (size_t)b * LH * KF;
    __half* FB = g_FBAR + (size_t)b * FBLD;
    for (int c2 = t; c2 < 344; c2 += 256) {
        int c = c2 * 2;
        float f0x = 0.f, f0y = 0.f, f1x = 0.f, f1y = 0.f;
        #pragma unroll
        for (int j = 0; j < LH; j++) {
            float2 v = __half22float2(*((const __half2*)(Fb + (size_t)j*KF) + c2));
            float w0 = ab2[0][j], w1 = ab2[1][j];
            f0x += w0 * v.x; f0y += w0 * v.y;
            f1x += w1 * v.x; f1y += w1 * v.y;
        }
        int o = (c < 344) ? c : c + 172;
        *((__half2*)(FB + o))       = __floats2half2_rn(f0x, f0y);
        *((__half2*)(FB + 896 + o)) = __floats2half2_rn(f1x, f1y);
    }
    for (int c2 = t; c2 < 86; c2 += 256) {
        float f0x = 0.f, f0y = 0.f, f1x = 0.f, f1y = 0.f;
        #pragma unroll
        for (int j = 0; j < LH; j++) {
            float2 v = __half22float2(*((const __half2*)(g_AE + (size_t)aid_s[j]*KP2) + c2));
            float w0 = ab2[0][j], w1 = ab2[1][j];
            f0x += w0 * v.x; f0y += w0 * v.y;
            f1x += w1 * v.x; f1y += w1 * v.y;
        }
        int o = 344 + c2 * 2;
        *((__half2*)(FB + o))       = __floats2half2_rn(f0x, f0y);
        *((__half2*)(FB + 896 + o)) = __floats2half2_rn(f1x, f1y);
    }
}

extern "C" void kernel_launch(void* const* d_in, const int* in_sizes, int n_in,
                              void* d_out, int out_size)
{
    const int*   nids       = (const int*)  d_in[0];
    const int*   hist_nids  = (const int*)  d_in[1];
    const int*   aids       = (const int*)  d_in[2];
    const int*   eids       = (const int*)  d_in[3];
    const float* hist_ts    = (const float*)d_in[4];
    const int*   dirs       = (const int*)  d_in[5];
    const float* node_emb   = (const float*)d_in[6];
    const float* edge_emb   = (const float*)d_in[7];
    const float* anony_emb  = (const float*)d_in[8];
    const float* time_w     = (const float*)d_in[9];
    const float* time_b     = (const float*)d_in[10];
    const float* in_proj_w  = (const float*)d_in[11];
    const float* in_proj_b  = (const float*)d_in[12];
    const float* out_proj_w = (const float*)d_in[13];
    const float* out_proj_b = (const float*)d_in[14];
    const float* outfn_w    = (const float*)d_in[15];
    const float* outfn_b    = (const float*)d_in[16];
    const float* fc1_w      = (const float*)d_in[17];
    const float* fc1_b      = (const float*)d_in[18];
    const float* fc2_w      = (const float*)d_in[19];
    const float* fc2_b      = (const float*)d_in[20];

    float* out = (float*)d_out;
    float* out_hr  = out + (size_t)BS * NF;
    float* out_pts = out + (size_t)2 * BS * NF;

    __half* F    = nullptr; cudaGetSymbolAddress((void**)&F,    g_F);
    __half* QKV  = nullptr; cudaGetSymbolAddress((void**)&QKV,  g_QKV);
    __half* FBAR = nullptr; cudaGetSymbolAddress((void**)&FBAR, g_FBAR);
    __half* CTXM = nullptr; cudaGetSymbolAddress((void**)&CTXM, g_CTXM);
    __half* OM   = nullptr; cudaGetSymbolAddress((void**)&OM,   g_OM);
    __half* X    = nullptr; cudaGetSymbolAddress((void**)&X,    g_X);
    __half* H1   = nullptr; cudaGetSymbolAddress((void**)&H1,   g_H1);
    __half* WR   = nullptr; cudaGetSymbolAddress((void**)&WR,   g_WR);
    __half* AE   = nullptr; cudaGetSymbolAddress((void**)&AE,   g_AE);
    __half* TA   = nullptr; cudaGetSymbolAddress((void**)&TA,   g_TA);
    int*    AOFF = nullptr; cudaGetSymbolAddress((void**)&AOFF, g_AOFF);
    float*  ZB   = nullptr; cudaGetSymbolAddress((void**)&ZB,   g_ZB);

    cudaFuncSetAttribute(gemm_f16, cudaFuncAttributeMaxDynamicSharedMemorySize, GSMEM);
    cudaFuncSetAttribute(attn_kernel, cudaFuncAttributeMaxDynamicSharedMemorySize, ATTN_SMEM);

    cvt_all<<<(C7 + 255)/256, 256>>>(in_proj_w, out_proj_w, outfn_w, fc1_w, fc2_w, anony_emb);

    build_kernel<<<NROWS, 256>>>(nids, hist_nids, aids, eids, hist_ts, dirs,
                                 node_emb, edge_emb, anony_emb, time_w, time_b,
                                 out_pts);

    // T_anon = AE @ W_anon^T  [128 x 1720], K=192, zero bias
    gemm_f16<<<dim3((QKN + GBN - 1)/GBN, 1), 256, GSMEM>>>(
        AE, WR + W_ANON, ZB, TA, QKN, nullptr, 0, nullptr,
        128, QKN, KP2, KP2, 0, nullptr, nullptr, 0, 0, 0, 0);

    // q|k = F @ W'^T + bias + T_anon[aoff]   [163840 x 1720], K=704
    gemm_f16<<<dim3((QKN + GBN - 1)/GBN, NROWS/GBM), 256, GSMEM>>>(
        F, WR + W_INPROJ, in_proj_b, QKV, QKN, nullptr, 0, nullptr,
        NROWS, QKN, KF, KF, 0, TA, AOFF, 0, 0, 0, 0);

    // attention: scores + softmax + abar + fbar (both heads in one pass)
    attn_kernel<<<BS, 256, ATTN_SMEM>>>(hist_nids);

    // ctx_mean (both heads, z-batched): fbar_h @ Wv_h^T + bv_h  [8192 x 430], K=896
    gemm_f16<<<dim3((430 + GBN - 1)/GBN, BS/GBM, 2), 256, GSMEM>>>(
        FBAR, WR + W_V, in_proj_b + QKN, CTXM, KP1, nullptr, 0, nullptr,
        BS, 430, KP1, FBLD, 0, nullptr, nullptr,
        896, 430 * KP1, 430, 430);

    // om = ctx_mean @ out_proj_w^T + b
    gemm_f16<<<dim3((DD + GBN - 1)/GBN, BS/GBM), 256, GSMEM>>>(
        CTXM, WR + W_OUTPROJ, out_proj_b, OM, KP1, nullptr, 0, nullptr,
        BS, DD, KP1, KP1, 0, nullptr, nullptr, 0, 0, 0, 0);

    // h_prev_left = relu(om) @ outfn_w^T + b  -> X + d_out
    gemm_f16<<<dim3((NF + GBN - 1)/GBN, BS/GBM), 256, GSMEM>>>(
        OM, WR + W_OUTFN, outfn_b, X, KP1, nullptr, 0, out,
        BS, NF, KP1, KP1, 1, nullptr, nullptr, 0, 0, 0, 0);

    // H1 = X @ fc1_w^T + b
    gemm_f16<<<dim3((NF + GBN - 1)/GBN, BS/GBM), 256, GSMEM>>>(
        X, WR + W_FC1, fc1_b, H1, KP2, nullptr, 0, nullptr,
        BS, NF, KP1, KP1, 0, nullptr, nullptr, 0, 0, 0, 0);

    // h_prev_right = relu(H1) @ fc2_w^T + b
    gemm_f16<<<dim3((NF + GBN - 1)/GBN, BS/GBM), 256, GSMEM>>>(
        H1, WR + W_FC2, fc2_b, nullptr, 0, out_hr, NF, nullptr,
        BS, NF, KP2, KP2, 1, nullptr, nullptr, 0, 0, 0, 0);
}

// round 17
// speedup vs baseline: 1.0877x; 1.0877x over previous
#include <cuda_runtime.h>
#include <cuda_fp16.h>
#include <cstdint>
#include <math.h>

#define BS 8192
#define LH 20
#define NF 172
#define TF 172
#define DD 860
#define DH 430
#define NROWS (BS*LH)
#define QKN 1720          // q|k only
#define KP1 896
#define KP2 192
#define KF  704           // reduced qkv K: src|dst|edge|time
#define FBLD 1792         // FBAR row stride (2 heads x 896)

// fp16 weight scratch offsets (halfs)
#define W_INPROJ 0                                     // [1720][704]
#define W_ANON   (W_INPROJ + (size_t)QKN*KF)           // [1720][192]
#define W_V      (W_ANON   + (size_t)QKN*KP2)          // [860][896]
#define W_OUTPROJ (W_V     + (size_t)DD*KP1)
#define W_OUTFN  (W_OUTPROJ + (size_t)DD*KP1)
#define W_FC1    (W_OUTFN  + (size_t)NF*KP1)
#define W_FC2    (W_FC1    + (size_t)NF*KP1)
#define W_TOTAL  (W_FC2    + (size_t)NF*KP2)

__device__ __half g_F[(size_t)NROWS * KF];
__device__ __half g_QKV[(size_t)NROWS * QKN];
__device__ __half g_FBAR[(size_t)BS * FBLD];
__device__ __half g_CTXM[(size_t)BS * KP1];
__device__ __half g_OM[(size_t)BS * KP1];
__device__ __half g_X[(size_t)BS * KP1];
__device__ __half g_H1[(size_t)BS * KP2];
__device__ __half g_WR[W_TOTAL];
__device__ __half g_AE[(size_t)128 * KP2];
__device__ __half g_TA[(size_t)128 * QKN];
__device__ int    g_AOFF[(size_t)NROWS];
__device__ int    g_AID[(size_t)NROWS];
__device__ float  g_ZB[QKN];

__device__ __forceinline__ uint32_t smem_u32(const void* p) {
    uint32_t a;
    asm("{ .reg .u64 t; cvta.to.shared.u64 t, %1; cvt.u32.u64 %0, t; }" : "=r"(a) : "l"(p));
    return a;
}
__device__ __forceinline__ void cp16(uint32_t dst, const void* src, int bytes) {
    asm volatile("cp.async.cg.shared.global [%0], [%1], 16, %2;"
                 :: "r"(dst), "l"(src), "r"(bytes));
}
__device__ __forceinline__ void cp_commit() {
    asm volatile("cp.async.commit_group;" ::: "memory");
}
template <int N>
__device__ __forceinline__ void cp_wait() {
    asm volatile("cp.async.wait_group %0;" :: "n"(N) : "memory");
}
__device__ __forceinline__ void mma_f16(float* c, const uint32_t* a, uint32_t b0, uint32_t b1) {
    asm volatile(
        "mma.sync.aligned.m16n8k16.row.col.f32.f16.f16.f32 "
        "{%0,%1,%2,%3}, {%4,%5,%6,%7}, {%8,%9}, {%0,%1,%2,%3};\n"
        : "+f"(c[0]), "+f"(c[1]), "+f"(c[2]), "+f"(c[3])
        : "r"(a[0]), "r"(a[1]), "r"(a[2]), "r"(a[3]), "r"(b0), "r"(b1));
}
__device__ __forceinline__ void ldsm_x4(uint32_t& r0, uint32_t& r1, uint32_t& r2, uint32_t& r3,
                                        uint32_t addr) {
    asm volatile("ldmatrix.sync.aligned.m8n8.x4.shared.b16 {%0,%1,%2,%3}, [%4];"
                 : "=r"(r0), "=r"(r1), "=r"(r2), "=r"(r3) : "r"(addr));
}

// ---------------- fused weight convert (+ anony embedding) ----------------
#define C0 (QKN*688)
#define C1 (C0 + QKN*NF)
#define C2 (C1 + DD*DD)
#define C3 (C2 + DD*DD)
#define C4 (C3 + NF*DD)
#define C5 (C4 + NF*DD)
#define C6 (C5 + NF*NF)
#define C7 (C6 + 21*NF)
__global__ void cvt_all(const float* __restrict__ w_inproj,
                        const float* __restrict__ w_outproj,
                        const float* __restrict__ w_outfn,
                        const float* __restrict__ w_fc1,
                        const float* __restrict__ w_fc2,
                        const float* __restrict__ anony_emb)
{
    int i = blockIdx.x * 256 + threadIdx.x;
    if (i >= C7) return;
    if (i < C0) {
        int r = i / 688, c = i % 688;
        int sc = (c < 344) ? c : c + 172;
        g_WR[W_INPROJ + (size_t)r * KF + c] = __float2half_rn(w_inproj[(size_t)r * DD + sc]);
    } else if (i < C1) {
        int j = i - C0; int r = j / NF, c = j % NF;
        g_WR[W_ANON + (size_t)r * KP2 + c] = __float2half_rn(w_inproj[(size_t)r * DD + 344 + c]);
    } else if (i < C2) {
        int j = i - C1; int r = j / DD, c = j % DD;
        g_WR[W_V + (size_t)r * KP1 + c] = __float2half_rn(w_inproj[(size_t)(QKN + r) * DD + c]);
    } else if (i < C3) {
        int j = i - C2; int r = j / DD, c = j % DD;
        g_WR[W_OUTPROJ + (size_t)r * KP1 + c] = __float2half_rn(w_outproj[j]);
    } else if (i < C4) {
        int j = i - C3; int r = j / DD, c = j % DD;
        g_WR[W_OUTFN + (size_t)r * KP1 + c] = __float2half_rn(w_outfn[j]);
    } else if (i < C5) {
        int j = i - C4; int r = j / DD, c = j % DD;
        g_WR[W_FC1 + (size_t)r * KP1 + c] = __float2half_rn(w_fc1[j]);
    } else if (i < C6) {
        int j = i - C5; int r = j / NF, c = j % NF;
        g_WR[W_FC2 + (size_t)r * KP2 + c] = __float2half_rn(w_fc2[j]);
    } else {
        int j = i - C6; int r = j / NF, c = j % NF;
        g_AE[(size_t)r * KP2 + c] = __float2half_rn(anony_emb[j]);
    }
}

// ---------------- fp16 GEMM, 128x128 tile, 3-stage, 2 CTA/SM, z-batched ----------------
#define GBM 128
#define GBN 128
#define A_BYTES (GBM * 144)
#define B_BYTES (GBN * 144)
#define STAGE_BYTES (A_BYTES + B_BYTES)
#define NSTAGE 3
#define GSMEM (NSTAGE * STAGE_BYTES)

__device__ __forceinline__ void issue_tile(const __half* __restrict__ A,
                                           const __half* __restrict__ B,
                                           uint32_t sstage, int m0, int n0, int k0,
                                           int N, int K, int lda, int t)
{
    #pragma unroll
    for (int i = 0; i < 4; i++) {
        int id = t + (i << 8);
        int row = id >> 3;
        int c8 = (id & 7) << 3;
        const __half* src = A + (size_t)(m0 + row) * lda + k0 + c8;
        cp16(sstage + row * 144 + (id & 7) * 16, src, 16);
    }
    #pragma unroll
    for (int i = 0; i < 4; i++) {
        int id = t + (i << 8);
        int row = id >> 3;
        int c8 = (id & 7) << 3;
        int bytes = (n0 + row < N) ? 16 : 0;
        const __half* src = bytes ? (B + (size_t)(n0 + row) * K + k0 + c8) : B;
        cp16(sstage + A_BYTES + row * 144 + (id & 7) * 16, src, bytes);
    }
}

__global__ void __launch_bounds__(256, 2)
gemm_f16(const __half* __restrict__ A, const __half* __restrict__ B,
         const float* __restrict__ bias,
         __half* __restrict__ C, int ldc,
         float* __restrict__ Cf, int ldcf,
         float* __restrict__ aux,
         int M, int N, int K, int lda, int relu_a,
         const __half* __restrict__ Ta, const int* __restrict__ aoff,
         int zA, int zB, int zBias, int zC)
{
    extern __shared__ __align__(16) char sm[];
    uint32_t sbase = smem_u32(sm);

    int z = blockIdx.z;
    A += (size_t)z * zA;
    B += (size_t)z * zB;
    bias += (size_t)z * zBias;
    if (C) C += (size_t)z * zC;

    int t = threadIdx.x;
    int warp = t >> 5, lane = t & 31;
    int m0 = blockIdx.y * GBM;
    int n0 = blockIdx.x * GBN;
    int mbase = (warp & 1) * 64;
    int nbase = (warp >> 1) * 32;

    uint32_t a_lane = (uint32_t)(lane & 15) * 144 + ((lane >> 4) << 4);
    uint32_t b_lane = (uint32_t)((lane & 7) | ((lane >> 1) & 8)) * 144 + (((lane >> 3) & 1) << 4);

    float acc[4][4][4];
    #pragma unroll
    for (int mi = 0; mi < 4; mi++)
        #pragma unroll
        for (int ni = 0; ni < 4; ni++)
            #pragma unroll
            for (int r = 0; r < 4; r++) acc[mi][ni][r] = 0.0f;

    int KT = K >> 6;

    issue_tile(A, B, sbase, m0, n0, 0, N, K, lda, t);
    cp_commit();
    if (KT > 1) issue_tile(A, B, sbase + STAGE_BYTES, m0, n0, 64, N, K, lda, t);
    cp_commit();

    const __half2 hz = __float2half2_rn(0.0f);

    int scur = 0, snxt = 2;
    for (int kt = 0; kt < KT; kt++) {
        cp_wait<1>();
        __syncthreads();

        if (kt + 2 < KT)
            issue_tile(A, B, sbase + snxt * STAGE_BYTES, m0, n0, (kt + 2) << 6, N, K, lda, t);
        cp_commit();

        uint32_t sA = sbase + scur * STAGE_BYTES;
        uint32_t sB = sA + A_BYTES;

        #pragma unroll
        for (int kk = 0; kk < 4; kk++) {
            uint32_t kof = (uint32_t)kk * 32;
            uint32_t a[4][4];
            #pragma unroll
            for (int mi = 0; mi < 4; mi++)
                ldsm_x4(a[mi][0], a[mi][1], a[mi][2], a[mi][3],
                        sA + (uint32_t)(mbase + mi * 16) * 144 + kof + a_lane);
            if (relu_a) {
                #pragma unroll
                for (int mi = 0; mi < 4; mi++)
                    #pragma unroll
                    for (int q = 0; q < 4; q++) {
                        __half2 h = *reinterpret_cast<__half2*>(&a[mi][q]);
                        h = __hmax2(h, hz);
                        a[mi][q] = *reinterpret_cast<uint32_t*>(&h);
                    }
            }
            uint32_t b[4][2];
            #pragma unroll
            for (int np = 0; np < 2; np++)
                ldsm_x4(b[2*np][0], b[2*np][1], b[2*np+1][0], b[2*np+1][1],
                        sB + (uint32_t)(nbase + np * 16) * 144 + kof + b_lane);
            #pragma unroll
            for (int mi = 0; mi < 4; mi++)
                #pragma unroll
                for (int ni = 0; ni < 4; ni++)
                    mma_f16(acc[mi][ni], a[mi], b[ni][0], b[ni][1]);
        }

        scur = (scur == NSTAGE - 1) ? 0 : scur + 1;
        snxt = (snxt == NSTAGE - 1) ? 0 : snxt + 1;
    }

    #pragma unroll
    for (int mi = 0; mi < 4; mi++) {
        int r0 = m0 + mbase + mi * 16 + (lane >> 2);
        int r1 = r0 + 8;
        int ao0 = aoff ? aoff[r0] : -1;
        int ao1 = aoff ? aoff[r1] : -1;
        #pragma unroll
        for (int ni = 0; ni < 4; ni++) {
            int col = n0 + nbase + ni * 8 + (lane & 3) * 2;
            if (col < N) {
                float b0 = bias[col], b1 = bias[col + 1];
                float v00 = acc[mi][ni][0] + b0, v01 = acc[mi][ni][1] + b1;
                float v10 = acc[mi][ni][2] + b0, v11 = acc[mi][ni][3] + b1;
                if (ao0 >= 0) {
                    float2 ta = __half22float2(*(const __half2*)(Ta + (size_t)ao0 + col));
                    v00 += ta.x; v01 += ta.y;
                }
                if (ao1 >= 0) {
                    float2 ta = __half22float2(*(const __half2*)(Ta + (size_t)ao1 + col));
                    v10 += ta.x; v11 += ta.y;
                }
                if (C) {
                    *(__half2*)(C + (size_t)r0 * ldc + col) = __floats2half2_rn(v00, v01);
                    *(__half2*)(C + (size_t)r1 * ldc + col) = __floats2half2_rn(v10, v11);
                }
                if (Cf) {
                    Cf[(size_t)r0 * ldcf + col]     = v00;
                    Cf[(size_t)r0 * ldcf + col + 1] = v01;
                    Cf[(size_t)r1 * ldcf + col]     = v10;
                    Cf[(size_t)r1 * ldcf + col + 1] = v11;
                }
                if (aux) {
                    aux[(size_t)r0 * N + col]     = v00;
                    aux[(size_t)r0 * N + col + 1] = v01;
                    aux[(size_t)r1 * N + col]     = v10;
                    aux[(size_t)r1 * N + col + 1] = v11;
                }
            }
        }
    }
}

// ---------------- build kernel ----------------
__global__ void build_kernel(const int* __restrict__ nids,
                             const int* __restrict__ hist_nids,
                             const int* __restrict__ aids,
                             const int* __restrict__ eids,
                             const float* __restrict__ ts,
                             const int* __restrict__ dirs,
                             const float* __restrict__ node_emb,
                             const float* __restrict__ edge_emb,
                             const float* __restrict__ anony_emb,
                             const float* __restrict__ time_w,
                             const float* __restrict__ time_b,
                             float* __restrict__ out_pts)
{
    int row = blockIdx.x;
    int b = row / LH, l = row % LH;
    int hn  = hist_nids[row];
    int d   = dirs[row];
    int rn  = nids[b];
    int src = d ? rn : hn;
    int dst = d ? hn : rn;
    int aid = aids[row];
    int eid = eids[row];
    float tlast = ts[b*LH + (LH-1)];
    float dt = tlast - ts[row];
    bool last = (l == LH-1);
    __half* Frow = g_F + (size_t)row * KF;

    for (int c = threadIdx.x; c < 688; c += blockDim.x) {
        float v;
        if (c < 516) {
            if (last) v = 0.0f;
            else if (c < 172) v = node_emb[(size_t)src*NF + c];
            else if (c < 344) v = node_emb[(size_t)dst*NF + (c-172)];
            else              v = edge_emb[(size_t)eid*NF + (c-344)];
        } else {
            int f = c - 516;
            v = cosf(dt * time_w[f] + time_b[f]);
        }
        Frow[c] = __float2half_rn(v);
    }

    if (last) {
        for (int c = threadIdx.x; c < 688; c += blockDim.x) {
            float v;
            if      (c < 172) v = node_emb[(size_t)src*NF + c];
            else if (c < 344) v = node_emb[(size_t)dst*NF + (c-172)];
            else if (c < 516) v = anony_emb[(size_t)aid*NF + (c-344)];
            else              v = edge_emb[(size_t)eid*NF + (c-516)];
            g_X[(size_t)b*KP1 + NF + c] = __float2half_rn(v);
        }
        if (threadIdx.x == 0) out_pts[b] = tlast;
    }
    if (threadIdx.x == 0) {
        int ae = last ? 21 : aid;
        g_AOFF[row] = ae * QKN;
        g_AID[row]  = ae;
    }
}

// ---------------- attention: HMMA scores + fbar emission (R15 version) ----------------
#define AST 456
#define ATILE_H (32 * AST)
#define ATTN_SMEM (2 * ATILE_H * 2)
#define DH2 215

__global__ void __launch_bounds__(256, 3)
attn_kernel(const int* __restrict__ hist_nids)
{
    extern __shared__ __align__(16) __half qkh[];
    __half* Qh = qkh;
    __half* Kh = qkh + ATILE_H;
    __shared__ float sc[LH][LH];
    __shared__ float ab2[2][LH];
    __shared__ int   msk[LH];
    __shared__ int   aid_s[LH];

    int b = blockIdx.x;
    int t = threadIdx.x;
    int warp = t >> 5, lane = t & 31;
    const __half* qkvb = g_QKV + (size_t)b * LH * QKN;
    const float scale = 0.048224282f;

    if (t < LH) {
        msk[t] = (hist_nids[b*LH + t] == 0 && t != LH-1) ? 1 : 0;
        aid_s[t] = g_AID[b*LH + t];
    }

    uint32_t qbase = smem_u32(Qh);
    uint32_t kbase = smem_u32(Kh);
    uint32_t a_lane = (uint32_t)(lane & 15) * 912 + ((lane >> 4) << 4);
    uint32_t b_lane = (uint32_t)((lane & 7) | ((lane >> 1) & 8)) * 912 + (((lane >> 3) & 1) << 4);

    for (int h = 0; h < 2; h++) {
        int off = h * DH;
        __syncthreads();
        const __half2 hz2 = __float2half2_rn(0.0f);
        for (int i = t; i < 32 * 228; i += 256) {
            int j = i / 228, c2 = i % 228;
            __half2 qv = hz2, kv = hz2;
            if (j < LH && c2 < DH2) {
                qv = *((const __half2*)(qkvb + (size_t)j*QKN + off) + c2);
                kv = *((const __half2*)(qkvb + (size_t)j*QKN + 860 + off) + c2);
            }
            *((__half2*)(Qh + j*AST) + c2) = qv;
            *((__half2*)(Kh + j*AST) + c2) = kv;
        }
        __syncthreads();

        if (warp < 4) {
            int mb = (warp & 1) * 16;
            int nb = (warp >> 1) * 16;
            float acc0[4] = {0.f, 0.f, 0.f, 0.f};
            float acc1[4] = {0.f, 0.f, 0.f, 0.f};
            uint32_t aaddr = qbase + (uint32_t)mb * 912 + a_lane;
            uint32_t baddr = kbase + (uint32_t)nb * 912 + b_lane;
            #pragma unroll
            for (int ks = 0; ks < 28; ks++) {
                uint32_t kof = (uint32_t)ks * 32;
                uint32_t a[4], b0r0, b0r1, b1r0, b1r1;
                ldsm_x4(a[0], a[1], a[2], a[3], aaddr + kof);
                ldsm_x4(b0r0, b0r1, b1r0, b1r1, baddr + kof);
                mma_f16(acc0, a, b0r0, b0r1);
                mma_f16(acc1, a, b1r0, b1r1);
            }
            int r0 = mb + (lane >> 2), r1 = r0 + 8;
            int c0 = nb + (lane & 3) * 2;
            if (r0 < LH) {
                if (c0     < LH) sc[r0][c0]     = acc0[0] * scale;
                if (c0 + 1 < LH) sc[r0][c0 + 1] = acc0[1] * scale;
                if (c0 + 8 < LH) sc[r0][c0 + 8] = acc1[0] * scale;
                if (c0 + 9 < LH) sc[r0][c0 + 9] = acc1[1] * scale;
            }
            if (r1 < LH) {
                if (c0     < LH) sc[r1][c0]     = acc0[2] * scale;
                if (c0 + 1 < LH) sc[r1][c0 + 1] = acc0[3] * scale;
                if (c0 + 8 < LH) sc[r1][c0 + 8] = acc1[2] * scale;
                if (c0 + 9 < LH) sc[r1][c0 + 9] = acc1[3] * scale;
            }
        }
        __syncthreads();

        if (warp == 0 && lane < LH) {
            int i = lane;
            float mx = -1e30f;
            #pragma unroll
            for (int j = 0; j < LH; j++)
                if (!msk[j]) mx = fmaxf(mx, sc[i][j]);
            float e[LH]; float s = 0.f;
            #pragma unroll
            for (int j = 0; j < LH; j++) {
                float ev = msk[j] ? 0.f : __expf(sc[i][j] - mx);
                e[j] = ev; s += ev;
            }
            float inv = 1.f / s;
            #pragma unroll
            for (int j = 0; j < LH; j++) sc[i][j] = e[j] * inv;
        }
        __syncthreads();

        if (warp == 0 && lane < LH) {
            int j = lane; float s = 0.f;
            #pragma unroll
            for (int i = 0; i < LH; i++) s += sc[i][j];
            ab2[h][j] = s * (1.0f / LH);
        }
        __syncthreads();
    }

    // fbar_h = sum_j ab2[h][j] * full_j (orig 860-col layout) -> FBAR
    const __half* Fb = g_F + (size_t)b * LH * KF;
    __half* FB = g_FBAR + (size_t)b * FBLD;
    for (int c2 = t; c2 < 344; c2 += 256) {
        int c = c2 * 2;
        float f0x = 0.f, f0y = 0.f, f1x = 0.f, f1y = 0.f;
        #pragma unroll
        for (int j = 0; j < LH; j++) {
            float2 v = __half22float2(*((const __half2*)(Fb + (size_t)j*KF) + c2));
            float w0 = ab2[0][j], w1 = ab2[1][j];
            f0x += w0 * v.x; f0y += w0 * v.y;
            f1x += w1 * v.x; f1y += w1 * v.y;
        }
        int o = (c < 344) ? c : c + 172;
        *((__half2*)(FB + o))       = __floats2half2_rn(f0x, f0y);
        *((__half2*)(FB + 896 + o)) = __floats2half2_rn(f1x, f1y);
    }
    for (int c2 = t; c2 < 86; c2 += 256) {
        float f0x = 0.f, f0y = 0.f, f1x = 0.f, f1y = 0.f;
        #pragma unroll
        for (int j = 0; j < LH; j++) {
            float2 v = __half22float2(*((const __half2*)(g_AE + (size_t)aid_s[j]*KP2) + c2));
            float w0 = ab2[0][j], w1 = ab2[1][j];
            f0x += w0 * v.x; f0y += w0 * v.y;
            f1x += w1 * v.x; f1y += w1 * v.y;
        }
        int o = 344 + c2 * 2;
        *((__half2*)(FB + o))       = __floats2half2_rn(f0x, f0y);
        *((__half2*)(FB + 896 + o)) = __floats2half2_rn(f1x, f1y);
    }
}

extern "C" void kernel_launch(void* const* d_in, const int* in_sizes, int n_in,
                              void* d_out, int out_size)
{
    const int*   nids       = (const int*)  d_in[0];
    const int*   hist_nids  = (const int*)  d_in[1];
    const int*   aids       = (const int*)  d_in[2];
    const int*   eids       = (const int*)  d_in[3];
    const float* hist_ts    = (const float*)d_in[4];
    const int*   dirs       = (const int*)  d_in[5];
    const float* node_emb   = (const float*)d_in[6];
    const float* edge_emb   = (const float*)d_in[7];
    const float* anony_emb  = (const float*)d_in[8];
    const float* time_w     = (const float*)d_in[9];
    const float* time_b     = (const float*)d_in[10];
    const float* in_proj_w  = (const float*)d_in[11];
    const float* in_proj_b  = (const float*)d_in[12];
    const float* out_proj_w = (const float*)d_in[13];
    const float* out_proj_b = (const float*)d_in[14];
    const float* outfn_w    = (const float*)d_in[15];
    const float* outfn_b    = (const float*)d_in[16];
    const float* fc1_w      = (const float*)d_in[17];
    const float* fc1_b      = (const float*)d_in[18];
    const float* fc2_w      = (const float*)d_in[19];
    const float* fc2_b      = (const float*)d_in[20];

    float* out = (float*)d_out;
    float* out_hr  = out + (size_t)BS * NF;
    float* out_pts = out + (size_t)2 * BS * NF;

    __half* F    = nullptr; cudaGetSymbolAddress((void**)&F,    g_F);
    __half* QKV  = nullptr; cudaGetSymbolAddress((void**)&QKV,  g_QKV);
    __half* FBAR = nullptr; cudaGetSymbolAddress((void**)&FBAR, g_FBAR);
    __half* CTXM = nullptr; cudaGetSymbolAddress((void**)&CTXM, g_CTXM);
    __half* OM   = nullptr; cudaGetSymbolAddress((void**)&OM,   g_OM);
    __half* X    = nullptr; cudaGetSymbolAddress((void**)&X,    g_X);
    __half* H1   = nullptr; cudaGetSymbolAddress((void**)&H1,   g_H1);
    __half* WR   = nullptr; cudaGetSymbolAddress((void**)&WR,   g_WR);
    __half* AE   = nullptr; cudaGetSymbolAddress((void**)&AE,   g_AE);
    __half* TA   = nullptr; cudaGetSymbolAddress((void**)&TA,   g_TA);
    int*    AOFF = nullptr; cudaGetSymbolAddress((void**)&AOFF, g_AOFF);
    float*  ZB   = nullptr; cudaGetSymbolAddress((void**)&ZB,   g_ZB);

    cudaFuncSetAttribute(gemm_f16, cudaFuncAttributeMaxDynamicSharedMemorySize, GSMEM);
    cudaFuncSetAttribute(attn_kernel, cudaFuncAttributeMaxDynamicSharedMemorySize, ATTN_SMEM);

    cvt_all<<<(C7 + 255)/256, 256>>>(in_proj_w, out_proj_w, outfn_w, fc1_w, fc2_w, anony_emb);

    build_kernel<<<NROWS, 256>>>(nids, hist_nids, aids, eids, hist_ts, dirs,
                                 node_emb, edge_emb, anony_emb, time_w, time_b,
                                 out_pts);

    // T_anon = AE @ W_anon^T  [128 x 1720], K=192, zero bias
    gemm_f16<<<dim3((QKN + GBN - 1)/GBN, 1), 256, GSMEM>>>(
        AE, WR + W_ANON, ZB, TA, QKN, nullptr, 0, nullptr,
        128, QKN, KP2, KP2, 0, nullptr, nullptr, 0, 0, 0, 0);

    // q|k = F @ W'^T + bias + T_anon[aoff]   [163840 x 1720], K=704
    gemm_f16<<<dim3((QKN + GBN - 1)/GBN, NROWS/GBM), 256, GSMEM>>>(
        F, WR + W_INPROJ, in_proj_b, QKV, QKN, nullptr, 0, nullptr,
        NROWS, QKN, KF, KF, 0, TA, AOFF, 0, 0, 0, 0);

    // attention: scores + softmax + abar + fbar
    attn_kernel<<<BS, 256, ATTN_SMEM>>>(hist_nids);

    // ctx_mean (both heads, z-batched): fbar_h @ Wv_h^T + bv_h  [8192 x 430], K=896
    gemm_f16<<<dim3((430 + GBN - 1)/GBN, BS/GBM, 2), 256, GSMEM>>>(
        FBAR, WR + W_V, in_proj_b + QKN, CTXM, KP1, nullptr, 0, nullptr,
        BS, 430, KP1, FBLD, 0, nullptr, nullptr,
        896, 430 * KP1, 430, 430);

    // om = ctx_mean @ out_proj_w^T + b
    gemm_f16<<<dim3((DD + GBN - 1)/GBN, BS/GBM), 256, GSMEM>>>(
        CTXM, WR + W_OUTPROJ, out_proj_b, OM, KP1, nullptr, 0, nullptr,
        BS, DD, KP1, KP1, 0, nullptr, nullptr, 0, 0, 0, 0);

    // h_prev_left = relu(om) @ outfn_w^T + b  -> X + d_out
    gemm_f16<<<dim3((NF + GBN - 1)/GBN, BS/GBM), 256, GSMEM>>>(
        OM, WR + W_OUTFN, outfn_b, X, KP1, nullptr, 0, out,
        BS, NF, KP1, KP1, 1, nullptr, nullptr, 0, 0, 0, 0);

    // H1 = X @ fc1_w^T + b
    gemm_f16<<<dim3((NF + GBN - 1)/GBN, BS/GBM), 256, GSMEM>>>(
        X, WR + W_FC1, fc1_b, H1, KP2, nullptr, 0, nullptr,
        BS, NF, KP1, KP1, 0, nullptr, nullptr, 0, 0, 0, 0);

    // h_prev_right = relu(H1) @ fc2_w^T + b
    gemm_f16<<<dim3((NF + GBN - 1)/GBN, BS/GBM), 256, GSMEM>>>(
        H1, WR + W_FC2, fc2_b, nullptr, 0, out_hr, NF, nullptr,
        BS, NF, KP2, KP2, 1, nullptr, nullptr, 0, 0, 0, 0);
}